// round 2
// baseline (speedup 1.0000x reference)
#include <cuda_runtime.h>
#include <cstdint>

#define S       512
#define BB      128
#define TMAX    2048
#define OBS     1024
#define CL      8            // cluster size (CTAs)
#define BPC     8            // batches per cluster
#define NSL     64           // S / CL : n-slice rows per CTA
#define NTHREADS 256
#define NCTAS   128          // 16 clusters * 8

// ---------------- device scratch (no allocs allowed) ----------------
__device__ float g_expAt[S * S];     // [p][n] : expA[n][p] transposed, column-softmax of transition
__device__ float g_expEt[OBS * S];   // [o][n] : row-softmax of emission, transposed
__device__ float g_expPi[S];

// ---------------- helpers ----------------
__device__ __forceinline__ float warp_max(float v) {
    #pragma unroll
    for (int o = 16; o; o >>= 1) v = fmaxf(v, __shfl_xor_sync(0xffffffffu, v, o));
    return v;
}
__device__ __forceinline__ float warp_sum(float v) {
    #pragma unroll
    for (int o = 16; o; o >>= 1) v += __shfl_xor_sync(0xffffffffu, v, o);
    return v;
}

__device__ __forceinline__ void st_remote_f2(uint32_t laddr, uint32_t trank, float c0, float c1) {
    asm volatile(
        "{\n\t"
        ".reg .b32 ra;\n\t"
        ".reg .b64 rv;\n\t"
        "mov.b64 rv, {%2, %3};\n\t"
        "mapa.shared::cluster.u32 ra, %0, %1;\n\t"
        "st.shared::cluster.b64 [ra], rv;\n\t"
        "}" :: "r"(laddr), "r"(trank), "f"(c0), "f"(c1) : "memory");
}

__device__ __forceinline__ void cluster_sync_() {
    asm volatile("barrier.cluster.arrive.aligned;\n" ::: "memory");
    asm volatile("barrier.cluster.wait.aligned;\n" ::: "memory");
}

// ---------------- prep kernels: linear-domain softmax tables ----------------
__global__ void prep_pi(const float* __restrict__ pi) {
    __shared__ float red[16];
    int tid = threadIdx.x;                 // 512 threads
    float v = pi[tid];
    float m = warp_max(v);
    if ((tid & 31) == 0) red[tid >> 5] = m;
    __syncthreads();
    float bm = red[0];
    #pragma unroll
    for (int i = 1; i < 16; i++) bm = fmaxf(bm, red[i]);
    __syncthreads();
    float e = expf(v - bm);
    float s = warp_sum(e);
    if ((tid & 31) == 0) red[tid >> 5] = s;
    __syncthreads();
    float bs = 0.f;
    #pragma unroll
    for (int i = 0; i < 16; i++) bs += red[i];
    g_expPi[tid] = e / bs;
}

// column softmax of transition (axis=0): block = column p, 128 threads x 4 rows
__global__ void prep_A(const float* __restrict__ trans) {
    __shared__ float red[4];
    int p = blockIdx.x, tid = threadIdx.x;
    int lane = tid & 31, w = tid >> 5;
    float v[4];
    #pragma unroll
    for (int k = 0; k < 4; k++) v[k] = trans[(tid + 128 * k) * S + p];
    float m = fmaxf(fmaxf(v[0], v[1]), fmaxf(v[2], v[3]));
    m = warp_max(m);
    if (lane == 0) red[w] = m;
    __syncthreads();
    float bm = fmaxf(fmaxf(red[0], red[1]), fmaxf(red[2], red[3]));
    __syncthreads();
    float e[4], s = 0.f;
    #pragma unroll
    for (int k = 0; k < 4; k++) { e[k] = expf(v[k] - bm); s += e[k]; }
    s = warp_sum(s);
    if (lane == 0) red[w] = s;
    __syncthreads();
    float bs = red[0] + red[1] + red[2] + red[3];
    float inv = 1.0f / bs;
    #pragma unroll
    for (int k = 0; k < 4; k++) g_expAt[p * S + tid + 128 * k] = e[k] * inv;
}

// row softmax of emission (axis=1), stored transposed [o][n]: block = row n, 256 threads x 4
__global__ void prep_E(const float* __restrict__ emis) {
    __shared__ float red[8];
    int n = blockIdx.x, tid = threadIdx.x;
    int lane = tid & 31, w = tid >> 5;
    float v[4];
    #pragma unroll
    for (int k = 0; k < 4; k++) v[k] = emis[n * OBS + tid + 256 * k];
    float m = fmaxf(fmaxf(v[0], v[1]), fmaxf(v[2], v[3]));
    m = warp_max(m);
    if (lane == 0) red[w] = m;
    __syncthreads();
    float bm = red[0];
    #pragma unroll
    for (int i = 1; i < 8; i++) bm = fmaxf(bm, red[i]);
    __syncthreads();
    float e[4], s = 0.f;
    #pragma unroll
    for (int k = 0; k < 4; k++) { e[k] = expf(v[k] - bm); s += e[k]; }
    s = warp_sum(s);
    if (lane == 0) red[w] = s;
    __syncthreads();
    float bs = 0.f;
    #pragma unroll
    for (int i = 0; i < 8; i++) bs += red[i];
    float inv = 1.0f / bs;
    #pragma unroll
    for (int k = 0; k < 4; k++) g_expEt[(tid + 256 * k) * S + n] = e[k] * inv;
}

// ---------------- main: scaled forward algorithm, 1 cluster = 8 batches ----------------
// smem (floats): As[S][NSL]=32768 | vs[2][BPC][S]=8192 | cpart[4][BPC][NSL]=2048 | rZs[8] | obs[8]
#define SMEM_FLOATS (S * NSL + 2 * BPC * S + 4 * BPC * NSL + 8 + 8)
#define SMEM_BYTES  (SMEM_FLOATS * 4 + 64)

__global__ void __cluster_dims__(CL, 1, 1) __launch_bounds__(NTHREADS, 1)
hmm_main(const int* __restrict__ x, const int* __restrict__ T, float* __restrict__ out) {
    extern __shared__ float sm[];
    float* As    = sm;                        // [p][nl]
    float* vs    = sm + S * NSL;              // [2][b][p]
    float* cpart = vs + 2 * BPC * S;          // [pq][b][nl]
    float* rZs   = cpart + 4 * BPC * NSL;     // [8]
    int*   obs_s = (int*)(rZs + 8);           // [8]
    __shared__ int Ts_sh[BPC];

    const int tid  = threadIdx.x;
    const int rank = blockIdx.x & (CL - 1);
    const int cid  = blockIdx.x >> 3;
    const int b0   = cid * BPC;
    const int lane = tid & 31, w = tid >> 5;
    const int nbase = rank * NSL;

    // resident expA slice: As[p][nl] = expA[nbase+nl][p]
    for (int i = tid; i < S * NSL; i += NTHREADS) {
        int p = i >> 6, nl = i & 63;
        As[i] = g_expAt[p * S + nbase + nl];
    }
    if (tid < BPC) {
        Ts_sh[tid]  = T[b0 + tid];
        obs_s[tid]  = x[(b0 + tid) * TMAX];
    }
    __syncthreads();

    int maxT = 0;
    #pragma unroll
    for (int b = 0; b < BPC; b++) maxT = max(maxT, Ts_sh[b]);
    const int Tl = Ts_sh[w];   // this warp's batch length
    float off = 0.f;           // log-scale offset (meaningful in lane 0)

    // v0[b][p] = expE[p, x_b0] * expPi[p]  (every CTA computes full copy)
    for (int i = tid; i < BPC * S; i += NTHREADS) {
        int b = i >> 9, p = i & (S - 1);
        vs[i] = g_expEt[obs_s[b] * S + p] * g_expPi[p];
    }
    __syncthreads();

    // scale/exchange mapping: thread handles elements (b2, nl2) and (b2, nl2+1)
    const int i0  = tid * 2;
    const int b2  = i0 >> 6;
    const int nl2 = i0 & 63;
    // matmul mapping
    const int pq = tid >> 6, nl = tid & 63;
    const int pbase = pq * 128;

    int cur = 0;
    for (int t = 1; ; ++t) {
        // observation for this step
        if (tid < BPC && t < TMAX) obs_s[tid] = x[(b0 + tid) * TMAX + t];

        // per-batch Z over current v (warp w <-> batch w)
        {
            const float* vb = vs + cur * BPC * S + w * S;
            float z = 0.f;
            #pragma unroll
            for (int k = 0; k < 16; k++) z += vb[lane + 32 * k];
            z = warp_sum(z);
            if (lane == 0) {
                float lz = logf(z);
                if (Tl == t && rank == 0) out[b0 + w] = off + lz;  // logsumexp at time t-1
                off += lz;
                rZs[w] = 1.0f / z;
            }
        }
        if (t == maxT) break;
        __syncthreads();

        // gather E column into regs (latency hidden by matmul)
        float2 e01 = *(const float2*)&g_expEt[obs_s[b2] * S + nbase + nl2];

        // matmul slice: acc[b] = sum_{p in quarter} v[b][p] * expA[nbase+nl][p]
        const float* vcur = vs + cur * BPC * S;
        float acc[BPC];
        #pragma unroll
        for (int b = 0; b < BPC; b++) acc[b] = 0.f;
        #pragma unroll 4
        for (int p = pbase; p < pbase + 128; p += 4) {
            float a0 = As[(p + 0) * NSL + nl];
            float a1 = As[(p + 1) * NSL + nl];
            float a2 = As[(p + 2) * NSL + nl];
            float a3 = As[(p + 3) * NSL + nl];
            #pragma unroll
            for (int b = 0; b < BPC; b++) {
                float4 v4 = *(const float4*)&vcur[b * S + p];
                acc[b] = fmaf(a3, v4.w, fmaf(a2, v4.z, fmaf(a1, v4.y, fmaf(a0, v4.x, acc[b]))));
            }
        }
        #pragma unroll
        for (int b = 0; b < BPC; b++) cpart[pq * (BPC * NSL) + b * NSL + nl] = acc[b];
        __syncthreads();

        // reduce partials, scale by E and 1/Z, broadcast to all cluster CTAs
        {
            int ci = b2 * NSL + nl2;
            float s0 = cpart[ci]     + cpart[512 + ci]     + cpart[1024 + ci]     + cpart[1536 + ci];
            float s1 = cpart[ci + 1] + cpart[512 + ci + 1] + cpart[1024 + ci + 1] + cpart[1536 + ci + 1];
            float r  = rZs[b2];
            float c0 = s0 * e01.x * r;
            float c1 = s1 * e01.y * r;
            int nxt = cur ^ 1;
            float* dst = vs + nxt * BPC * S + b2 * S + nbase + nl2;
            dst[0] = c0; dst[1] = c1;                       // self
            uint32_t laddr = (uint32_t)__cvta_generic_to_shared(dst);
            #pragma unroll
            for (int r2 = 0; r2 < CL; r2++)
                if (r2 != rank) st_remote_f2(laddr, (uint32_t)r2, c0, c1);
        }
        cluster_sync_();   // drains DSMEM stores; doubles as block barrier
        cur ^= 1;
    }
}

// ---------------- launch ----------------
extern "C" void kernel_launch(void* const* d_in, const int* in_sizes, int n_in,
                              void* d_out, int out_size) {
    const int*   x     = (const int*)d_in[0];
    const int*   T     = (const int*)d_in[1];
    const float* pi    = (const float*)d_in[2];
    const float* trans = (const float*)d_in[3];
    const float* emis  = (const float*)d_in[4];
    float* out = (float*)d_out;

    cudaFuncSetAttribute(hmm_main, cudaFuncAttributeMaxDynamicSharedMemorySize, SMEM_BYTES);

    prep_pi<<<1, S>>>(pi);
    prep_A<<<S, 128>>>(trans);
    prep_E<<<S, 256>>>(emis);
    hmm_main<<<NCTAS, NTHREADS, SMEM_BYTES>>>(x, T, out);
}

// round 4
// speedup vs baseline: 1.1013x; 1.1013x over previous
#include <cuda_runtime.h>
#include <cstdint>

#define S       512
#define TMAXX   2048
#define OBS     1024
#define CL      8            // cluster size (CTAs)
#define BPC     8            // batches per cluster
#define NSL     64           // S / CL : n-slice per CTA
#define NT      512
#define NCTAS   128          // 16 clusters * 8

// ---- shared memory layout (float offsets) ----
#define ASTRIDE 516                      // padded p-stride for As rows (conflict-free v2.u64)
#define AS_F    0                        // As[nl][p] : 64 x 516
#define VS_F    (AS_F + NSL * ASTRIDE)   // vs[2][b][p] : 2 x 8 x 512
#define CP_F    (VS_F + 2 * BPC * S)     // cpart[pq][b][nl] : 8 x 8 x 64
#define ZP_F    (CP_F + 8 * BPC * NSL)   // zparts[2][rank][b] : 2 x 8 x 8
#define RZ_F    (ZP_F + 2 * CL * BPC)    // rZ[8]
#define TS_F    (RZ_F + 8)               // T[8] (ints)
#define SMEM_FLOATS (TS_F + 8)
#define SMEM_BYTES  (SMEM_FLOATS * 4)

// ---------------- device tables ----------------
__device__ float g_expA[S * S];      // [n][p] : column-softmax of transition
__device__ float g_expEt[OBS * S];   // [o][n] : row-softmax of emission, transposed
__device__ float g_expPi[S];

// ---------------- helpers ----------------
__device__ __forceinline__ float warp_max(float v) {
    #pragma unroll
    for (int o = 16; o; o >>= 1) v = fmaxf(v, __shfl_xor_sync(0xffffffffu, v, o));
    return v;
}
__device__ __forceinline__ float warp_sum(float v) {
    #pragma unroll
    for (int o = 16; o; o >>= 1) v += __shfl_xor_sync(0xffffffffu, v, o);
    return v;
}
__device__ __forceinline__ unsigned long long ffma2(unsigned long long a, unsigned long long b,
                                                    unsigned long long c) {
    unsigned long long d;
    asm("fma.rn.f32x2 %0, %1, %2, %3;" : "=l"(d) : "l"(a), "l"(b), "l"(c));
    return d;
}
__device__ __forceinline__ void lds_2x64(uint32_t addr, unsigned long long& a, unsigned long long& b) {
    asm volatile("ld.shared.v2.u64 {%0, %1}, [%2];" : "=l"(a), "=l"(b) : "r"(addr));
}
__device__ __forceinline__ void sts_f2(uint32_t addr, float c0, float c1) {
    asm volatile("{\n\t.reg .b64 rv;\n\tmov.b64 rv, {%1, %2};\n\t"
                 "st.shared.b64 [%0], rv;\n\t}"
                 :: "r"(addr), "f"(c0), "f"(c1) : "memory");
}
__device__ __forceinline__ void stc_f2(uint32_t addr, float c0, float c1) {
    asm volatile("{\n\t.reg .b64 rv;\n\tmov.b64 rv, {%1, %2};\n\t"
                 "st.shared::cluster.b64 [%0], rv;\n\t}"
                 :: "r"(addr), "f"(c0), "f"(c1) : "memory");
}
__device__ __forceinline__ void stc_f1(uint32_t addr, float c) {
    asm volatile("st.shared::cluster.b32 [%0], %1;" :: "r"(addr), "f"(c) : "memory");
}
__device__ __forceinline__ uint32_t mapa_u32(uint32_t addr, int rank) {
    uint32_t r;
    asm("mapa.shared::cluster.u32 %0, %1, %2;" : "=r"(r) : "r"(addr), "r"(rank));
    return r;
}
__device__ __forceinline__ void cluster_sync_() {
    asm volatile("barrier.cluster.arrive.aligned;\n" ::: "memory");
    asm volatile("barrier.cluster.wait.aligned;\n" ::: "memory");
}

// ---------------- prep kernels ----------------
__global__ void prep_pi(const float* __restrict__ pi) {
    __shared__ float red[16];
    int tid = threadIdx.x;                 // 512 threads
    float v = pi[tid];
    float m = warp_max(v);
    if ((tid & 31) == 0) red[tid >> 5] = m;
    __syncthreads();
    float bm = red[0];
    #pragma unroll
    for (int i = 1; i < 16; i++) bm = fmaxf(bm, red[i]);
    __syncthreads();
    float e = expf(v - bm);
    float s = warp_sum(e);
    if ((tid & 31) == 0) red[tid >> 5] = s;
    __syncthreads();
    float bs = 0.f;
    #pragma unroll
    for (int i = 0; i < 16; i++) bs += red[i];
    g_expPi[tid] = e / bs;
}

// column softmax of transition (axis=0): block = column p, stored [n][p]
__global__ void prep_A(const float* __restrict__ trans) {
    __shared__ float red[4];
    int p = blockIdx.x, tid = threadIdx.x;
    int lane = tid & 31, w = tid >> 5;
    float v[4];
    #pragma unroll
    for (int k = 0; k < 4; k++) v[k] = trans[(tid + 128 * k) * S + p];
    float m = fmaxf(fmaxf(v[0], v[1]), fmaxf(v[2], v[3]));
    m = warp_max(m);
    if (lane == 0) red[w] = m;
    __syncthreads();
    float bm = fmaxf(fmaxf(red[0], red[1]), fmaxf(red[2], red[3]));
    __syncthreads();
    float e[4], s = 0.f;
    #pragma unroll
    for (int k = 0; k < 4; k++) { e[k] = expf(v[k] - bm); s += e[k]; }
    s = warp_sum(s);
    if (lane == 0) red[w] = s;
    __syncthreads();
    float bs = red[0] + red[1] + red[2] + red[3];
    float inv = 1.0f / bs;
    #pragma unroll
    for (int k = 0; k < 4; k++) g_expA[(tid + 128 * k) * S + p] = e[k] * inv;
}

// row softmax of emission (axis=1), stored transposed [o][n]
__global__ void prep_E(const float* __restrict__ emis) {
    __shared__ float red[8];
    int n = blockIdx.x, tid = threadIdx.x;
    int lane = tid & 31, w = tid >> 5;
    float v[4];
    #pragma unroll
    for (int k = 0; k < 4; k++) v[k] = emis[n * OBS + tid + 256 * k];
    float m = fmaxf(fmaxf(v[0], v[1]), fmaxf(v[2], v[3]));
    m = warp_max(m);
    if (lane == 0) red[w] = m;
    __syncthreads();
    float bm = red[0];
    #pragma unroll
    for (int i = 1; i < 8; i++) bm = fmaxf(bm, red[i]);
    __syncthreads();
    float e[4], s = 0.f;
    #pragma unroll
    for (int k = 0; k < 4; k++) { e[k] = expf(v[k] - bm); s += e[k]; }
    s = warp_sum(s);
    if (lane == 0) red[w] = s;
    __syncthreads();
    float bs = 0.f;
    #pragma unroll
    for (int i = 0; i < 8; i++) bs += red[i];
    float inv = 1.0f / bs;
    #pragma unroll
    for (int k = 0; k < 4; k++) g_expEt[(tid + 256 * k) * S + n] = e[k] * inv;
}

// ---------------- main: scaled forward, deferred normalization ----------------
__global__ void __cluster_dims__(CL, 1, 1) __launch_bounds__(NT, 1)
hmm_main(const int* __restrict__ x, const int* __restrict__ T, float* __restrict__ out) {
    extern __shared__ float smf[];
    int* Ts_sh = (int*)(smf + TS_F);

    const int tid  = threadIdx.x;
    const int rank = blockIdx.x & (CL - 1);
    const int cid  = blockIdx.x >> 3;
    const int b0   = cid * BPC;
    const int lane = tid & 31, w = tid >> 5;
    const int nbase = rank * NSL;

    const uint32_t smb = (uint32_t)__cvta_generic_to_shared(smf);

    // hoisted peer base addresses
    uint32_t rb[CL];
    #pragma unroll
    for (int r = 0; r < CL; r++) rb[r] = mapa_u32(smb, r);

    // --- init: resident A slice As[nl][p] (padded stride) ---
    for (int i = tid; i < NSL * S; i += NT) {
        int nl = i >> 9, p = i & (S - 1);
        smf[AS_F + nl * ASTRIDE + p] = g_expA[(nbase + nl) * S + p];
    }
    if (tid < BPC) Ts_sh[tid] = T[b0 + tid];

    // --- init: v0[b][p] = expE[p, x_b0] * expPi[p]  (full copy per CTA) ---
    for (int i = tid; i < BPC * S; i += NT) {
        int b = i >> 9, p = i & (S - 1);
        int xb = __ldg(&x[(b0 + b) * TMAXX]);
        smf[VS_F + i] = g_expEt[xb * S + p] * g_expPi[p];
    }
    __syncthreads();

    // --- init: zparts[0][r][b] : full sum in slot r=0, zeros elsewhere ---
    if (w < BPC) {
        float z = 0.f;
        #pragma unroll
        for (int k = 0; k < 16; k++) z += smf[VS_F + w * S + lane + 32 * k];
        z = warp_sum(z);
        if (lane == 0) {
            smf[ZP_F + 0 * CL * BPC + 0 * BPC + w] = z;
            #pragma unroll
            for (int r = 1; r < CL; r++) smf[ZP_F + r * BPC + w] = 0.f;
        }
    }
    __syncthreads();

    int maxT = 0;
    #pragma unroll
    for (int b = 0; b < BPC; b++) maxT = max(maxT, Ts_sh[b]);

    // matmul mapping: 8 p-groups of 64, 64 n each
    const int pq = tid >> 6, nl = tid & 63;
    const int pbase = pq * 64;
    const uint32_t as_addr = smb + (AS_F + nl * ASTRIDE + pbase) * 4u;

    // scale-phase mapping (tid < 256): 2 adjacent n per thread
    const int b2  = tid >> 5;          // warp w == batch b2
    const int nl2 = (tid & 31) * 2;

    float off = 0.f;   // per-batch log-offset (lane 0 of warps 0..7)
    int cur = 0;

    for (int t = 1; ; ++t) {
        const int nxt = cur ^ 1;

        // ---- prefetch E column for this step (hidden under matmul) ----
        float2 e01;
        if (tid < 256) {
            int tt = t < TMAXX ? t : TMAXX - 1;
            int xb = __ldg(&x[(b0 + b2) * TMAXX + tt]);
            e01 = *(const float2*)&g_expEt[xb * S + nbase + nl2];
        }

        // ---- Z_{t-1} from partials; log accumulation; rZ (lane0 of warps 0..7) ----
        if (lane == 0 && w < BPC) {
            float z = 0.f;
            #pragma unroll
            for (int r = 0; r < CL; r++) z += smf[ZP_F + cur * CL * BPC + r * BPC + w];
            float lz = logf(z);
            if (rank == 0 && Ts_sh[w] == t) out[b0 + w] = off + lz;
            off += lz;
            smf[RZ_F + w] = 1.0f / z;
        }
        if (t == maxT) break;

        // ---- matmul slice: acc2[b] = packed sum over p-pairs of v[b][p]*As[nl][p] ----
        {
            const uint32_t vbase = smb + (VS_F + cur * BPC * S + pbase) * 4u;
            unsigned long long acc[BPC];
            #pragma unroll
            for (int b = 0; b < BPC; b++) acc[b] = 0ull;
            #pragma unroll
            for (int k = 0; k < 16; k++) {
                unsigned long long a01, a23;
                lds_2x64(as_addr + k * 16u, a01, a23);
                #pragma unroll
                for (int b = 0; b < BPC; b++) {
                    unsigned long long v01, v23;
                    lds_2x64(vbase + b * 2048u + k * 16u, v01, v23);
                    acc[b] = ffma2(v01, a01, acc[b]);
                    acc[b] = ffma2(v23, a23, acc[b]);
                }
            }
            #pragma unroll
            for (int b = 0; b < BPC; b++) {
                float lo, hi;
                asm("mov.b64 {%0, %1}, %2;" : "=f"(lo), "=f"(hi) : "l"(acc[b]));
                smf[CP_F + pq * (BPC * NSL) + b * NSL + nl] = lo + hi;
            }
        }
        __syncthreads();

        // ---- scale + broadcast + Z partials (tid < 256: 2 elems each) ----
        if (tid < 256) {
            int ci = b2 * NSL + nl2;
            float s0 = 0.f, s1 = 0.f;
            #pragma unroll
            for (int q = 0; q < 8; q++) {
                float2 cp = *(const float2*)&smf[CP_F + q * (BPC * NSL) + ci];
                s0 += cp.x; s1 += cp.y;
            }
            float r = smf[RZ_F + b2];
            float c0 = s0 * e01.x * r;
            float c1 = s1 * e01.y * r;

            uint32_t voff = (VS_F + nxt * BPC * S + b2 * S + nbase + nl2) * 4u;
            sts_f2(smb + voff, c0, c1);                 // self: plain SMEM store
            #pragma unroll
            for (int rr = 0; rr < CL; rr++)
                if (rr != rank) stc_f2(rb[rr] + voff, c0, c1);

            float zp = warp_sum(c0 + c1);
            if (lane == 0) {
                uint32_t zoff = (ZP_F + nxt * CL * BPC + rank * BPC + b2) * 4u;
                #pragma unroll
                for (int rr = 0; rr < CL; rr++) stc_f1(rb[rr] + zoff, zp);
            }
        }

        cluster_sync_();   // drains DSMEM stores; doubles as block barrier
        cur = nxt;
    }
}

// ---------------- launch ----------------
extern "C" void kernel_launch(void* const* d_in, const int* in_sizes, int n_in,
                              void* d_out, int out_size) {
    const int*   x     = (const int*)d_in[0];
    const int*   T     = (const int*)d_in[1];
    const float* pi    = (const float*)d_in[2];
    const float* trans = (const float*)d_in[3];
    const float* emis  = (const float*)d_in[4];
    float* out = (float*)d_out;

    cudaFuncSetAttribute(hmm_main, cudaFuncAttributeMaxDynamicSharedMemorySize, SMEM_BYTES);

    prep_pi<<<1, S>>>(pi);
    prep_A<<<S, 128>>>(trans);
    prep_E<<<S, 256>>>(emis);
    hmm_main<<<NCTAS, NT, SMEM_BYTES>>>(x, T, out);
}

// round 5
// speedup vs baseline: 1.4522x; 1.3187x over previous
#include <cuda_runtime.h>
#include <cstdint>

#define S       512
#define TMAXX   2048
#define OBS     1024
#define CL      8            // cluster size (CTAs)
#define BPC     8            // batches per cluster
#define NSL     64           // S / CL
#define NT      512
#define NCTAS   128          // 16 clusters * 8

// slice payload: c[8][68-padded rows, 64 used] + zp[8] = 552 floats = 2208 bytes
#define BROW    68
#define SLICE_F 552
#define SLICE_B 2208

// ---- dynamic smem layout (float offsets) ----
#define VS_F    0                         // vs2[2][8 slices][SLICE_F]
#define CP_F    (VS_F + 2 * CL * SLICE_F) // cpart[8][8][64] = 4096
#define ZR_F    (CP_F + 4096)             // zred[16]
#define BAR_F   (ZR_F + 16)               // full[2][8] (16 u64) + empty[2] (2 u64) = 36 floats
#define TS_F    (BAR_F + 36)              // Ts[8] ints
#define SMEM_FLOATS (TS_F + 8)
#define SMEM_BYTES  (SMEM_FLOATS * 4)

// ---------------- device tables ----------------
__device__ float g_expA[S * S];      // [n][p]
__device__ float g_expEt[OBS * S];   // [o][n]
__device__ float g_expPi[S];

// ---------------- helpers ----------------
__device__ __forceinline__ float warp_max(float v) {
    #pragma unroll
    for (int o = 16; o; o >>= 1) v = fmaxf(v, __shfl_xor_sync(0xffffffffu, v, o));
    return v;
}
__device__ __forceinline__ float warp_sum(float v) {
    #pragma unroll
    for (int o = 16; o; o >>= 1) v += __shfl_xor_sync(0xffffffffu, v, o);
    return v;
}
__device__ __forceinline__ unsigned long long ffma2(unsigned long long a, unsigned long long b,
                                                    unsigned long long c) {
    unsigned long long d;
    asm("fma.rn.f32x2 %0, %1, %2, %3;" : "=l"(d) : "l"(a), "l"(b), "l"(c));
    return d;
}
__device__ __forceinline__ void lds_2x64(uint32_t addr, unsigned long long& a, unsigned long long& b) {
    asm volatile("ld.shared.v2.u64 {%0, %1}, [%2];" : "=l"(a), "=l"(b) : "r"(addr));
}
__device__ __forceinline__ uint32_t mapa_u32(uint32_t addr, int rank) {
    uint32_t r;
    asm("mapa.shared::cluster.u32 %0, %1, %2;" : "=r"(r) : "r"(addr), "r"(rank));
    return r;
}
__device__ __forceinline__ void mbar_init(uint32_t addr, uint32_t cnt) {
    asm volatile("mbarrier.init.shared.b64 [%0], %1;" :: "r"(addr), "r"(cnt) : "memory");
}
__device__ __forceinline__ void mbar_arrive_expect(uint32_t addr, uint32_t tx) {
    asm volatile("mbarrier.arrive.expect_tx.shared.b64 _, [%0], %1;" :: "r"(addr), "r"(tx) : "memory");
}
__device__ __forceinline__ void mbar_arrive_remote(uint32_t remAddr) {
    asm volatile("mbarrier.arrive.shared::cluster.b64 _, [%0];" :: "r"(remAddr) : "memory");
}
__device__ __forceinline__ void mbar_wait(uint32_t addr, uint32_t parity) {
    uint32_t done;
    asm volatile(
        "{\n\t.reg .pred p;\n\t"
        "mbarrier.try_wait.parity.acquire.cta.shared::cta.b64 p, [%1], %2;\n\t"
        "selp.b32 %0, 1, 0, p;\n\t}"
        : "=r"(done) : "r"(addr), "r"(parity) : "memory");
    if (!done) {
        asm volatile(
            "{\n\t.reg .pred P1;\n\t"
            "WL_%=:\n\t"
            "mbarrier.try_wait.parity.acquire.cta.shared::cta.b64 P1, [%0], %1, 0x989680;\n\t"
            "@P1 bra.uni WD_%=;\n\t"
            "bra.uni WL_%=;\n\t"
            "WD_%=:\n\t}"
            :: "r"(addr), "r"(parity) : "memory");
    }
}
__device__ __forceinline__ void bulk_s2s(uint32_t dst_cluster, uint32_t src_cta,
                                         uint32_t bytes, uint32_t mbar_cluster) {
    asm volatile(
        "cp.async.bulk.shared::cluster.shared::cta.mbarrier::complete_tx::bytes [%0], [%1], %2, [%3];"
        :: "r"(dst_cluster), "r"(src_cta), "r"(bytes), "r"(mbar_cluster) : "memory");
}
__device__ __forceinline__ void fence_proxy_async_() {
    asm volatile("fence.proxy.async.shared::cta;" ::: "memory");
}
__device__ __forceinline__ void cluster_sync_() {
    asm volatile("barrier.cluster.arrive.aligned;\n" ::: "memory");
    asm volatile("barrier.cluster.wait.aligned;\n" ::: "memory");
}

// ---------------- prep kernels (unchanged math) ----------------
__global__ void prep_pi(const float* __restrict__ pi) {
    __shared__ float red[16];
    int tid = threadIdx.x;
    float v = pi[tid];
    float m = warp_max(v);
    if ((tid & 31) == 0) red[tid >> 5] = m;
    __syncthreads();
    float bm = red[0];
    #pragma unroll
    for (int i = 1; i < 16; i++) bm = fmaxf(bm, red[i]);
    __syncthreads();
    float e = expf(v - bm);
    float s = warp_sum(e);
    if ((tid & 31) == 0) red[tid >> 5] = s;
    __syncthreads();
    float bs = 0.f;
    #pragma unroll
    for (int i = 0; i < 16; i++) bs += red[i];
    g_expPi[tid] = e / bs;
}

__global__ void prep_A(const float* __restrict__ trans) {
    __shared__ float red[4];
    int p = blockIdx.x, tid = threadIdx.x;
    int lane = tid & 31, w = tid >> 5;
    float v[4];
    #pragma unroll
    for (int k = 0; k < 4; k++) v[k] = trans[(tid + 128 * k) * S + p];
    float m = fmaxf(fmaxf(v[0], v[1]), fmaxf(v[2], v[3]));
    m = warp_max(m);
    if (lane == 0) red[w] = m;
    __syncthreads();
    float bm = fmaxf(fmaxf(red[0], red[1]), fmaxf(red[2], red[3]));
    __syncthreads();
    float e[4], s = 0.f;
    #pragma unroll
    for (int k = 0; k < 4; k++) { e[k] = expf(v[k] - bm); s += e[k]; }
    s = warp_sum(s);
    if (lane == 0) red[w] = s;
    __syncthreads();
    float bs = red[0] + red[1] + red[2] + red[3];
    float inv = 1.0f / bs;
    #pragma unroll
    for (int k = 0; k < 4; k++) g_expA[(tid + 128 * k) * S + p] = e[k] * inv;
}

__global__ void prep_E(const float* __restrict__ emis) {
    __shared__ float red[8];
    int n = blockIdx.x, tid = threadIdx.x;
    int lane = tid & 31, w = tid >> 5;
    float v[4];
    #pragma unroll
    for (int k = 0; k < 4; k++) v[k] = emis[n * OBS + tid + 256 * k];
    float m = fmaxf(fmaxf(v[0], v[1]), fmaxf(v[2], v[3]));
    m = warp_max(m);
    if (lane == 0) red[w] = m;
    __syncthreads();
    float bm = red[0];
    #pragma unroll
    for (int i = 1; i < 8; i++) bm = fmaxf(bm, red[i]);
    __syncthreads();
    float e[4], s = 0.f;
    #pragma unroll
    for (int k = 0; k < 4; k++) { e[k] = expf(v[k] - bm); s += e[k]; }
    s = warp_sum(s);
    if (lane == 0) red[w] = s;
    __syncthreads();
    float bs = 0.f;
    #pragma unroll
    for (int i = 0; i < 8; i++) bs += red[i];
    float inv = 1.0f / bs;
    #pragma unroll
    for (int k = 0; k < 4; k++) g_expEt[(tid + 256 * k) * S + n] = e[k] * inv;
}

// ---------------- main ----------------
__global__ void __cluster_dims__(CL, 1, 1) __launch_bounds__(NT, 1)
hmm_main(const int* __restrict__ x, const int* __restrict__ T, float* __restrict__ out) {
    extern __shared__ float smf[];
    int* Ts_sh = (int*)(smf + TS_F);

    const int tid  = threadIdx.x;
    const int rank = blockIdx.x & (CL - 1);
    const int cid  = blockIdx.x >> 3;
    const int b0   = cid * BPC;
    const int lane = tid & 31;
    const int nbase = rank * NSL;

    const uint32_t smb = (uint32_t)__cvta_generic_to_shared(smf);
    const uint32_t bar0 = smb + BAR_F * 4u;          // full[s][src] = bar0 + (s*8+src)*8
    const uint32_t ebar0 = bar0 + 16 * 8;            // empty[s] = ebar0 + s*8

    // matmul mapping: group pq handles slice pq (64 p), thread covers 1 n-row, 8 batches
    const int pq  = tid >> 6;
    const int nlm = tid & 63;
    // scale mapping: thread covers (bs, nls)
    const int bs  = tid >> 6;
    const int nls = tid & 63;

    // ---- mbarrier init + initial arms ----
    if (tid == 0) {
        #pragma unroll
        for (int s = 0; s < 2; s++) {
            #pragma unroll
            for (int src = 0; src < CL; src++) mbar_init(bar0 + (s * 8 + src) * 8, 1);
            mbar_init(ebar0 + s * 8, CL);
        }
        #pragma unroll
        for (int s = 0; s < 2; s++)
            #pragma unroll
            for (int src = 0; src < CL; src++)
                if (src != rank) mbar_arrive_expect(bar0 + (s * 8 + src) * 8, SLICE_B);
    }
    if (tid < BPC) Ts_sh[tid] = T[b0 + tid];

    // ---- init v0 into buffer 0 (full local copy, slice layout) ----
    for (int j = tid; j < CL * BPC * NSL; j += NT) {
        int src = j >> 9, b = (j >> 6) & 7, nl = j & 63;
        int p = src * NSL + nl;
        int xb = __ldg(&x[(b0 + b) * TMAXX]);
        smf[VS_F + src * SLICE_F + b * BROW + nl] = g_expEt[xb * S + p] * g_expPi[p];
    }
    __syncthreads();
    if (tid < 64) {
        int src = tid >> 3, b = tid & 7;
        float z = 0.f;
        for (int nl = 0; nl < NSL; nl++) z += smf[VS_F + src * SLICE_F + b * BROW + nl];
        smf[VS_F + src * SLICE_F + 8 * BROW + b] = z;   // zp slot (544 + b)
    }

    // ---- load A slice into registers: thread (pq,nlm) -> A[nbase+nlm][pq*64 .. +64) ----
    unsigned long long Ar[32];
    {
        const float* ab = &g_expA[(nbase + nlm) * S + pq * NSL];
        #pragma unroll
        for (int c = 0; c < 16; c++) {
            float4 a4 = *(const float4*)(ab + 4 * c);
            asm("mov.b64 %0, {%1, %2};" : "=l"(Ar[2 * c])     : "f"(a4.x), "f"(a4.y));
            asm("mov.b64 %0, {%1, %2};" : "=l"(Ar[2 * c + 1]) : "f"(a4.z), "f"(a4.w));
        }
    }
    __syncthreads();
    cluster_sync_();   // barriers + init data visible cluster-wide before any comm

    int maxT = 0;
    #pragma unroll
    for (int b = 0; b < BPC; b++) maxT = max(maxT, Ts_sh[b]);
    const int Tb = Ts_sh[bs];

    float off = 0.f;
    int cur = 0;
    uint32_t pf0 = 0, pf1 = 0;       // full-wait parities per buffer (this thread's group barrier)
    uint32_t pe0 = 0, pe1 = 0;       // empty-wait parities (lane 0 of warp 0 only)

    for (int t = 1; ; ++t) {
        const int nxt = cur ^ 1;
        const uint32_t vcur = smb + (VS_F + cur * CL * SLICE_F) * 4u;

        // ---- prefetch E column + observation (hidden under matmul) ----
        int tt = t < TMAXX ? t : TMAXX - 1;
        int xb = __ldg(&x[(b0 + bs) * TMAXX + tt]);
        float Ee = __ldg(&g_expEt[xb * S + nbase + nls]);

        // ---- wait my group's slice (own slice and t==1 need no wait) ----
        if (t > 1 && pq != rank) {
            mbar_wait(bar0 + (cur * 8 + pq) * 8, cur ? pf1 : pf0);
        }

        // ---- matmul: acc[b] += v[b][p] * A (A in regs), p in slice pq ----
        {
            const uint32_t vg = vcur + (pq * SLICE_F) * 4u;
            unsigned long long acc[BPC];
            #pragma unroll
            for (int b = 0; b < BPC; b++) acc[b] = 0ull;
            #pragma unroll
            for (int c = 0; c < 16; c++) {
                #pragma unroll
                for (int b = 0; b < BPC; b++) {
                    unsigned long long v01, v23;
                    lds_2x64(vg + (b * BROW + 4 * c) * 4u, v01, v23);
                    acc[b] = ffma2(v01, Ar[2 * c], acc[b]);
                    acc[b] = ffma2(v23, Ar[2 * c + 1], acc[b]);
                }
            }
            #pragma unroll
            for (int b = 0; b < BPC; b++) {
                float lo, hi;
                asm("mov.b64 {%0, %1}, %2;" : "=f"(lo), "=f"(hi) : "l"(acc[b]));
                smf[CP_F + pq * (BPC * NSL) + b * NSL + nlm] = lo + hi;
            }
        }
        if (t > 1) { if (cur) pf1 ^= 1; else pf0 ^= 1; }
        __syncthreads();   // sync#1: all slices consumed, cpart complete, zp[cur] visible

        // ---- per-thread Z of v_t (redundant, no serialization) ----
        {
            float z = 0.f;
            #pragma unroll
            for (int src = 0; src < CL; src++)
                z += smf[VS_F + cur * CL * SLICE_F + src * SLICE_F + 8 * BROW + bs];
            float tot = off + logf(z);
            if (nls == 0 && rank == 0 && Tb == t) out[b0 + bs] = tot;
            off = tot;
            if (t == maxT) break;

            float rz = 1.0f / z;

            // ---- reduce partials, scale, store own slice of v_{t+1} ----
            float ssum = 0.f;
            #pragma unroll
            for (int q = 0; q < 8; q++) ssum += smf[CP_F + q * (BPC * NSL) + bs * NSL + nls];
            float c = ssum * Ee * rz;
            smf[VS_F + nxt * CL * SLICE_F + rank * SLICE_F + bs * BROW + nls] = c;
            float zs = warp_sum(c);
            if (lane == 0) smf[ZR_F + (tid >> 5)] = zs;
        }
        __syncthreads();   // sync#2: slice + zred complete

        // ---- housekeeping + comm (warp 0 only) ----
        if (tid < 32) {
            if (lane < 8) {
                // zp for own slice of v_{t+1}
                smf[VS_F + nxt * CL * SLICE_F + rank * SLICE_F + 8 * BROW + lane] =
                    smf[ZR_F + 2 * lane] + smf[ZR_F + 2 * lane + 1];
            } else if (lane < 16) {
                // re-arm full[cur][src] for its next fill (skip at t==1: init armed it)
                int src = lane - 8;
                if (t > 1 && src != rank) mbar_arrive_expect(bar0 + (cur * 8 + src) * 8, SLICE_B);
                if (t > 1 && src == 7 && rank == 7) {} // no-op balance
            }
            __syncwarp();
            if (lane >= 16 && lane < 24) {
                // tell all CTAs buffer cur is free (ordered after re-arm)
                mbar_arrive_remote(mapa_u32(ebar0 + cur * 8, lane - 16));
            }
            if (lane == 0) {
                // gate copies on peers done reading buffer nxt (skip at t==1: never read)
                if (t > 1) {
                    mbar_wait(ebar0 + nxt * 8, nxt ? pe1 : pe0);
                    if (nxt) pe1 ^= 1; else pe0 ^= 1;
                }
                fence_proxy_async_();
                uint32_t srcaddr = smb + (VS_F + nxt * CL * SLICE_F + rank * SLICE_F) * 4u;
                #pragma unroll
                for (int r = 0; r < CL; r++) {
                    if (r == rank) continue;
                    uint32_t dst = mapa_u32(srcaddr, r);
                    uint32_t mb  = mapa_u32(bar0 + (nxt * 8 + rank) * 8, r);
                    bulk_s2s(dst, srcaddr, SLICE_B, mb);
                }
            }
        }
        cur = nxt;
    }
}

// ---------------- launch ----------------
extern "C" void kernel_launch(void* const* d_in, const int* in_sizes, int n_in,
                              void* d_out, int out_size) {
    const int*   x     = (const int*)d_in[0];
    const int*   T     = (const int*)d_in[1];
    const float* pi    = (const float*)d_in[2];
    const float* trans = (const float*)d_in[3];
    const float* emis  = (const float*)d_in[4];
    float* out = (float*)d_out;

    cudaFuncSetAttribute(hmm_main, cudaFuncAttributeMaxDynamicSharedMemorySize, SMEM_BYTES);

    prep_pi<<<1, S>>>(pi);
    prep_A<<<S, 128>>>(trans);
    prep_E<<<S, 256>>>(emis);
    hmm_main<<<NCTAS, NT, SMEM_BYTES>>>(x, T, out);
}